// round 1
// baseline (speedup 1.0000x reference)
#include <cuda_runtime.h>
#include <math.h>

// Problem constants (fixed by setup_inputs)
#define NB   4
#define SEQ  2048
#define EMB  1024
#define NH   16
#define HD   64
#define MTOT (NB*SEQ*NH)          // 131072 head-rows
// softmax scale: 1/sqrt(EMB) = 1/32 (reference scales by sqrt(embed_size))
#define QSCALE 0.03125f

// Scratch (static device globals; no allocation allowed)
__device__ float g_Qp[NB*SEQ*EMB];
__device__ float g_Kp[NB*SEQ*EMB];
__device__ float g_Vp[NB*SEQ*EMB];
__device__ float g_O [NB*SEQ*EMB];

// ---------------------------------------------------------------------------
// Kernel 1: fused per-head-dim projections.
//   Treat each input as [MTOT][64]; out_row = x_row @ W^T  (W is [64][64]).
//   Q output pre-scaled by 1/32 to fold the softmax scale.
//   2 rows per thread for W-register reuse (8 FMA per LDS.128 -> FMA-bound).
// ---------------------------------------------------------------------------
__global__ __launch_bounds__(256)
void proj_kernel(const float* __restrict__ Vin, const float* __restrict__ Kin,
                 const float* __restrict__ Qin,
                 const float* __restrict__ Wv, const float* __restrict__ Wk,
                 const float* __restrict__ Wq)
{
    __shared__ float4 Wsh[3][64*16];    // 48 KB: Wq, Wk, Wv as float4 rows
    const int tid = threadIdx.x;
    for (int i = tid; i < 64*16; i += 256) {
        Wsh[0][i] = ((const float4*)Wq)[i];
        Wsh[1][i] = ((const float4*)Wk)[i];
        Wsh[2][i] = ((const float4*)Wv)[i];
    }
    __syncthreads();

    const float* in[3]  = {Qin, Kin, Vin};
    float*       out[3] = {g_Qp, g_Kp, g_Vp};

    const long rowBase = (long)blockIdx.x * 512;   // gridDim.x = MTOT/512 = 256
    const long r0 = rowBase + tid;
    const long r1 = rowBase + 256 + tid;

    #pragma unroll 1
    for (int t = 0; t < 3; t++) {
        const float scale = (t == 0) ? QSCALE : 1.0f;
        const float4* src = (const float4*)in[t];
        float4*       dst = (float4*)out[t];

        float4 x0[16], x1[16];
        #pragma unroll
        for (int d = 0; d < 16; d++) { x0[d] = src[r0*16 + d]; x1[d] = src[r1*16 + d]; }

        #pragma unroll 1
        for (int e4 = 0; e4 < 16; e4++) {
            float o0[4], o1[4];
            #pragma unroll
            for (int u = 0; u < 4; u++) {
                const int e = e4*4 + u;
                float a0 = 0.f, a1 = 0.f;
                #pragma unroll
                for (int d = 0; d < 16; d++) {
                    const float4 w = Wsh[t][e*16 + d];
                    a0 += x0[d].x*w.x; a0 += x0[d].y*w.y; a0 += x0[d].z*w.z; a0 += x0[d].w*w.w;
                    a1 += x1[d].x*w.x; a1 += x1[d].y*w.y; a1 += x1[d].z*w.z; a1 += x1[d].w*w.w;
                }
                o0[u] = a0 * scale; o1[u] = a1 * scale;
            }
            dst[r0*16 + e4] = make_float4(o0[0], o0[1], o0[2], o0[3]);
            dst[r1*16 + e4] = make_float4(o1[0], o1[1], o1[2], o1[3]);
        }
    }
}

// ---------------------------------------------------------------------------
// Kernel 2: flash attention, fp32.
//   Block = (q-tile of 128, one (n,h)); 256 threads as 16x16; thread tile 8q x 4{k|d}.
//   Online softmax kept per-thread, replicated across the 16 lanes that share a
//   row (shfl_xor over lane bits 0..3).
//   Smem: Qs[128][64] row-major, Kt[64][65] d-major (conflict-free),
//         Vs[64][64], Ps[128][68].  Total 100,608 B (dynamic).
// ---------------------------------------------------------------------------
#define BM 128
#define BN 64
#define ATTN_SMEM ((BM*64 + 64*65 + 64*64 + BM*68) * sizeof(float))

__global__ __launch_bounds__(256)
void attn_kernel()
{
    extern __shared__ float sm[];
    float* Qs = sm;                    // [BM][64]
    float* Kt = Qs + BM*64;            // [64][65]  (transposed K, padded)
    float* Vs = Kt + 64*65;            // [BN][64]
    float* Ps = Vs + 64*64;            // [BM][68]

    const int tid = threadIdx.x;
    const int tx = tid & 15;           // k/d column group
    const int ty = tid >> 4;           // q row group

    const int qtile = blockIdx.x;      // 0..15
    const int nh    = blockIdx.y;      // 0..63
    const int n = nh >> 4, h = nh & 15;

    const float* Qg = g_Qp + (long)n*SEQ*EMB + h*HD;
    const float* Kg = g_Kp + (long)n*SEQ*EMB + h*HD;
    const float* Vg = g_Vp + (long)n*SEQ*EMB + h*HD;
    float*       Og = g_O  + (long)n*SEQ*EMB + h*HD;

    const int q0 = qtile * BM;

    // load Q tile (coalesced along d)
    for (int idx = tid; idx < BM*64; idx += 256) {
        const int q = idx >> 6, d = idx & 63;
        Qs[q*64 + d] = Qg[(long)(q0 + q)*EMB + d];
    }

    float m_i[8], l_i[8], acc_o[8][4];
    #pragma unroll
    for (int i = 0; i < 8; i++) {
        m_i[i] = -1e30f; l_i[i] = 0.f;
        #pragma unroll
        for (int j = 0; j < 4; j++) acc_o[i][j] = 0.f;
    }

    for (int kt = 0; kt < SEQ/BN; kt++) {
        const int k0 = kt * BN;
        // load K (transposed into Kt) and V
        for (int idx = tid; idx < BN*64; idx += 256) {
            const int k = idx >> 6, d = idx & 63;
            const float kv = Kg[(long)(k0 + k)*EMB + d];
            Kt[d*65 + k] = kv;
            Vs[k*64 + d] = Vg[(long)(k0 + k)*EMB + d];
        }
        __syncthreads();

        // S = Q K^T  (Q already scaled)
        float s[8][4];
        #pragma unroll
        for (int i = 0; i < 8; i++)
            #pragma unroll
            for (int j = 0; j < 4; j++) s[i][j] = 0.f;

        #pragma unroll 8
        for (int d = 0; d < 64; d++) {
            float a[8], b[4];
            #pragma unroll
            for (int i = 0; i < 8; i++) a[i] = Qs[(ty*8 + i)*64 + d];
            #pragma unroll
            for (int j = 0; j < 4; j++) b[j] = Kt[d*65 + tx*4 + j];
            #pragma unroll
            for (int i = 0; i < 8; i++)
                #pragma unroll
                for (int j = 0; j < 4; j++) s[i][j] += a[i]*b[j];
        }

        // online softmax per row (16 lanes share a row -> xor-reduce bits 0..3)
        #pragma unroll
        for (int i = 0; i < 8; i++) {
            float mx = fmaxf(fmaxf(s[i][0], s[i][1]), fmaxf(s[i][2], s[i][3]));
            #pragma unroll
            for (int o = 1; o < 16; o <<= 1)
                mx = fmaxf(mx, __shfl_xor_sync(0xffffffffu, mx, o));
            const float mnew  = fmaxf(m_i[i], mx);
            const float alpha = __expf(m_i[i] - mnew);
            float rs = 0.f;
            #pragma unroll
            for (int j = 0; j < 4; j++) { s[i][j] = __expf(s[i][j] - mnew); rs += s[i][j]; }
            #pragma unroll
            for (int o = 1; o < 16; o <<= 1)
                rs += __shfl_xor_sync(0xffffffffu, rs, o);
            l_i[i] = l_i[i]*alpha + rs;
            m_i[i] = mnew;
            #pragma unroll
            for (int j = 0; j < 4; j++) acc_o[i][j] *= alpha;
            #pragma unroll
            for (int j = 0; j < 4; j++) Ps[(ty*8 + i)*68 + tx*4 + j] = s[i][j];
        }
        __syncthreads();

        // O += P V
        #pragma unroll 8
        for (int k = 0; k < BN; k++) {
            float p[8], v[4];
            #pragma unroll
            for (int i = 0; i < 8; i++) p[i] = Ps[(ty*8 + i)*68 + k];
            #pragma unroll
            for (int j = 0; j < 4; j++) v[j] = Vs[k*64 + tx*4 + j];
            #pragma unroll
            for (int i = 0; i < 8; i++)
                #pragma unroll
                for (int j = 0; j < 4; j++) acc_o[i][j] += p[i]*v[j];
        }
        __syncthreads();
    }

    // epilogue: normalize and store (O layout == (N,S,E) with head-major cols)
    #pragma unroll
    for (int i = 0; i < 8; i++) {
        const float inv = 1.0f / l_i[i];
        const long q = q0 + ty*8 + i;
        #pragma unroll
        for (int j = 0; j < 4; j++)
            Og[q*EMB + tx*4 + j] = acc_o[i][j] * inv;
    }
}

// ---------------------------------------------------------------------------
// Kernel 3: output projection  C[8192,1024] = O @ Wo^T + bo.
//   Both O and Wo are K-major (NT GEMM). Tiles 128x64x32, thread tile 8x4.
//   Smem tiles stored k-major (transposed) so all inner reads are
//   broadcast / consecutive -> conflict-free.
// ---------------------------------------------------------------------------
#define CBM 128
#define CBN 64
#define CBK 32

__global__ __launch_bounds__(256)
void outproj_kernel(const float* __restrict__ Wo, const float* __restrict__ bo,
                    float* __restrict__ Cout)
{
    __shared__ float As[CBK][CBM + 1];   // [k][m]
    __shared__ float Bs[CBK][CBN + 1];   // [k][e]

    const int tid = threadIdx.x;
    const int tx = tid & 15, ty = tid >> 4;
    const int mbase = blockIdx.x * CBM;  // gridDim.x = 8192/128 = 64
    const int ebase = blockIdx.y * CBN;  // gridDim.y = 1024/64 = 16
    const float* A = g_O;

    float acc[8][4];
    #pragma unroll
    for (int i = 0; i < 8; i++)
        #pragma unroll
        for (int j = 0; j < 4; j++) acc[i][j] = 0.f;

    for (int kb = 0; kb < EMB; kb += CBK) {
        for (int idx = tid; idx < CBM*CBK; idx += 256) {
            const int m = idx >> 5, k = idx & 31;
            As[k][m] = A[(long)(mbase + m)*EMB + kb + k];
        }
        for (int idx = tid; idx < CBN*CBK; idx += 256) {
            const int e = idx >> 5, k = idx & 31;
            Bs[k][e] = Wo[(long)(ebase + e)*EMB + kb + k];
        }
        __syncthreads();

        #pragma unroll 8
        for (int k = 0; k < CBK; k++) {
            float a[8], b[4];
            #pragma unroll
            for (int i = 0; i < 8; i++) a[i] = As[k][ty*8 + i];
            #pragma unroll
            for (int j = 0; j < 4; j++) b[j] = Bs[k][tx*4 + j];
            #pragma unroll
            for (int i = 0; i < 8; i++)
                #pragma unroll
                for (int j = 0; j < 4; j++) acc[i][j] += a[i]*b[j];
        }
        __syncthreads();
    }

    #pragma unroll
    for (int j = 0; j < 4; j++) {
        const float bias = bo[ebase + tx*4 + j];
        #pragma unroll
        for (int i = 0; i < 8; i++)
            Cout[(long)(mbase + ty*8 + i)*EMB + ebase + tx*4 + j] = acc[i][j] + bias;
    }
}

// ---------------------------------------------------------------------------
// Launch.  Inputs (metadata order): values, keys, query, Wv, Wk, Wq, Wo, bo.
// ---------------------------------------------------------------------------
extern "C" void kernel_launch(void* const* d_in, const int* in_sizes, int n_in,
                              void* d_out, int out_size)
{
    const float* Vin = (const float*)d_in[0];
    const float* Kin = (const float*)d_in[1];
    const float* Qin = (const float*)d_in[2];
    const float* Wv  = (const float*)d_in[3];
    const float* Wk  = (const float*)d_in[4];
    const float* Wq  = (const float*)d_in[5];
    const float* Wo  = (const float*)d_in[6];
    const float* bo  = (const float*)d_in[7];
    float* out = (float*)d_out;

    // opt-in to >48KB dynamic smem for the attention kernel (host-side call,
    // executes immediately; not a stream op, safe under graph capture)
    cudaFuncSetAttribute(attn_kernel, cudaFuncAttributeMaxDynamicSharedMemorySize,
                         (int)ATTN_SMEM);

    proj_kernel<<<MTOT/512, 256>>>(Vin, Kin, Qin, Wv, Wk, Wq);
    attn_kernel<<<dim3(16, NB*NH), 256, ATTN_SMEM>>>();
    outproj_kernel<<<dim3((NB*SEQ)/CBM, EMB/CBN), 256>>>(Wo, bo, out);
}

// round 2
// speedup vs baseline: 1.9420x; 1.9420x over previous
#include <cuda_runtime.h>
#include <math.h>
#include <stdint.h>

// Problem constants (fixed by setup_inputs)
#define NB   4
#define SEQ  2048
#define EMB  1024
#define NH   16
#define HD   64
#define MTOT (NB*SEQ*NH)          // 131072 head-rows
#define QSCALE 0.03125f           // 1/sqrt(EMB): folded into Q

// Scratch (static device globals; no runtime allocation allowed)
__device__ float g_Qp[NB*SEQ*EMB];
__device__ float g_Kp[NB*SEQ*EMB];
__device__ float g_Vp[NB*SEQ*EMB];
__device__ float g_O [NB*SEQ*EMB];

// ---------------------------------------------------------------------------
// Helpers: tf32 round-to-nearest, and m16n8k8 tf32 mma
// ---------------------------------------------------------------------------
__device__ __forceinline__ float tf32r(float x) {
    uint32_t u;
    asm("cvt.rna.tf32.f32 %0, %1;" : "=r"(u) : "f"(x));
    return __uint_as_float(u);
}
__device__ __forceinline__ uint32_t fau(float x) { return __float_as_uint(x); }

__device__ __forceinline__ void mma_tf32(float* c, const uint32_t* a,
                                         uint32_t b0, uint32_t b1) {
    asm volatile(
        "mma.sync.aligned.m16n8k8.row.col.f32.tf32.tf32.f32 "
        "{%0,%1,%2,%3}, {%4,%5,%6,%7}, {%8,%9}, {%0,%1,%2,%3};\n"
        : "+f"(c[0]), "+f"(c[1]), "+f"(c[2]), "+f"(c[3])
        : "r"(a[0]), "r"(a[1]), "r"(a[2]), "r"(a[3]), "r"(b0), "r"(b1));
}

// ---------------------------------------------------------------------------
// Kernel 1: fused per-head-dim projections (fp32 FFMA; outputs tf32-rounded).
// ---------------------------------------------------------------------------
__global__ __launch_bounds__(256)
void proj_kernel(const float* __restrict__ Vin, const float* __restrict__ Kin,
                 const float* __restrict__ Qin,
                 const float* __restrict__ Wv, const float* __restrict__ Wk,
                 const float* __restrict__ Wq)
{
    __shared__ float4 Wsh[3][64*16];    // 48 KB: Wq, Wk, Wv as float4 rows
    const int tid = threadIdx.x;
    for (int i = tid; i < 64*16; i += 256) {
        Wsh[0][i] = ((const float4*)Wq)[i];
        Wsh[1][i] = ((const float4*)Wk)[i];
        Wsh[2][i] = ((const float4*)Wv)[i];
    }
    __syncthreads();

    const float* in[3]  = {Qin, Kin, Vin};
    float*       out[3] = {g_Qp, g_Kp, g_Vp};

    const long rowBase = (long)blockIdx.x * 512;   // gridDim.x = 256
    const long r0 = rowBase + tid;
    const long r1 = rowBase + 256 + tid;

    #pragma unroll 1
    for (int t = 0; t < 3; t++) {
        const float scale = (t == 0) ? QSCALE : 1.0f;
        const float4* src = (const float4*)in[t];
        float4*       dst = (float4*)out[t];

        float4 x0[16], x1[16];
        #pragma unroll
        for (int d = 0; d < 16; d++) { x0[d] = src[r0*16 + d]; x1[d] = src[r1*16 + d]; }

        #pragma unroll 1
        for (int e4 = 0; e4 < 16; e4++) {
            float o0[4], o1[4];
            #pragma unroll
            for (int u = 0; u < 4; u++) {
                const int e = e4*4 + u;
                float a0 = 0.f, a1 = 0.f;
                #pragma unroll
                for (int d = 0; d < 16; d++) {
                    const float4 w = Wsh[t][e*16 + d];
                    a0 += x0[d].x*w.x; a0 += x0[d].y*w.y; a0 += x0[d].z*w.z; a0 += x0[d].w*w.w;
                    a1 += x1[d].x*w.x; a1 += x1[d].y*w.y; a1 += x1[d].z*w.z; a1 += x1[d].w*w.w;
                }
                o0[u] = tf32r(a0 * scale); o1[u] = tf32r(a1 * scale);
            }
            dst[r0*16 + e4] = make_float4(o0[0], o0[1], o0[2], o0[3]);
            dst[r1*16 + e4] = make_float4(o1[0], o1[1], o1[2], o1[3]);
        }
    }
}

// ---------------------------------------------------------------------------
// Kernel 2: flash attention, tf32 mma.sync (m16n8k8).
//   Block: 256 thr = 8 warps; q-tile 128 (16 rows/warp); K-tile 64 keys.
//   Smem: Ks[64][68] (k-major), Vs[64][72] (k-major), Ps: 8 x [16][68]
//   All fragment LDS patterns bank-conflict-free by pad construction:
//     K b-frag bank = (4g + t + 8s) mod 32  (bijective)
//     V b-frag bank = (8t + g + 8dt) mod 32 (bijective)
//     P a-frag bank = (4g + t + 8ks) mod 32 (bijective)
// ---------------------------------------------------------------------------
#define PADK 68
#define PADV 72
#define PADP 68
#define ATTN_SMEM ((64*PADK + 64*PADV + 8*16*PADP) * sizeof(float))

__global__ __launch_bounds__(256, 1)
void attn_kernel()
{
    extern __shared__ float sm[];
    float* Ks = sm;                    // [64][PADK]
    float* Vs = Ks + 64*PADK;          // [64][PADV]
    float* Ps = Vs + 64*PADV;          // 8 x [16][PADP]

    const int tid  = threadIdx.x;
    const int lane = tid & 31;
    const int w    = tid >> 5;
    const int g    = lane >> 2;        // mma group id (row within 8)
    const int t    = lane & 3;         // thread-in-group

    float* Pw = Ps + w * 16 * PADP;

    const int qtile = blockIdx.x;      // 0..15
    const int nh    = blockIdx.y;      // 0..63
    const int n = nh >> 4, h = nh & 15;

    const float* Qg = g_Qp + (long)n*SEQ*EMB + h*HD;
    const float* Kg = g_Kp + (long)n*SEQ*EMB + h*HD;
    const float* Vg = g_Vp + (long)n*SEQ*EMB + h*HD;
    float*       Og = g_O  + (long)n*SEQ*EMB + h*HD;

    const int qw = qtile * 128 + w * 16;   // this warp's first q row

    // ---- stage Q tile (16x64) through Pw, then read A-fragments into regs
    for (int i = lane; i < 16*64; i += 32) {
        const int r = i >> 6, d = i & 63;
        Pw[r*PADP + d] = Qg[(long)(qw + r)*EMB + d];
    }
    __syncwarp();
    uint32_t qa[8][4];
    #pragma unroll
    for (int s = 0; s < 8; s++) {
        qa[s][0] = fau(Pw[ g     *PADP + s*8 + t    ]);
        qa[s][1] = fau(Pw[(g + 8)*PADP + s*8 + t    ]);
        qa[s][2] = fau(Pw[ g     *PADP + s*8 + t + 4]);
        qa[s][3] = fau(Pw[(g + 8)*PADP + s*8 + t + 4]);
    }

    float oacc[8][4];
    #pragma unroll
    for (int i = 0; i < 8; i++)
        #pragma unroll
        for (int j = 0; j < 4; j++) oacc[i][j] = 0.f;
    float m0 = -1e30f, m1 = -1e30f, l0 = 0.f, l1 = 0.f;

    for (int kt = 0; kt < SEQ/64; kt++) {
        const int k0 = kt * 64;
        __syncthreads();
        // load K and V tiles (coalesced; conflict-free STS)
        for (int i = tid; i < 64*64; i += 256) {
            const int k = i >> 6, d = i & 63;
            Ks[k*PADK + d] = Kg[(long)(k0 + k)*EMB + d];
            Vs[k*PADV + d] = Vg[(long)(k0 + k)*EMB + d];
        }
        __syncthreads();

        // ---- S = Q K^T (128x64 per block; 16x64 per warp)
        float sf[8][4];
        #pragma unroll
        for (int i = 0; i < 8; i++)
            #pragma unroll
            for (int j = 0; j < 4; j++) sf[i][j] = 0.f;

        #pragma unroll
        for (int s = 0; s < 8; s++) {
            #pragma unroll
            for (int nt = 0; nt < 8; nt++) {
                const uint32_t b0 = fau(Ks[(nt*8 + g)*PADK + s*8 + t    ]);
                const uint32_t b1 = fau(Ks[(nt*8 + g)*PADK + s*8 + t + 4]);
                mma_tf32(sf[nt], qa[s], b0, b1);
            }
        }

        // ---- online softmax (rows g and g+8; quad lanes share a row)
        float mx0 = -1e30f, mx1 = -1e30f;
        #pragma unroll
        for (int nt = 0; nt < 8; nt++) {
            mx0 = fmaxf(mx0, fmaxf(sf[nt][0], sf[nt][1]));
            mx1 = fmaxf(mx1, fmaxf(sf[nt][2], sf[nt][3]));
        }
        #pragma unroll
        for (int o = 1; o < 4; o <<= 1) {
            mx0 = fmaxf(mx0, __shfl_xor_sync(0xffffffffu, mx0, o));
            mx1 = fmaxf(mx1, __shfl_xor_sync(0xffffffffu, mx1, o));
        }
        const float mn0 = fmaxf(m0, mx0), mn1 = fmaxf(m1, mx1);
        const float al0 = __expf(m0 - mn0), al1 = __expf(m1 - mn1);
        float rs0 = 0.f, rs1 = 0.f;
        #pragma unroll
        for (int nt = 0; nt < 8; nt++) {
            sf[nt][0] = __expf(sf[nt][0] - mn0); rs0 += sf[nt][0];
            sf[nt][1] = __expf(sf[nt][1] - mn0); rs0 += sf[nt][1];
            sf[nt][2] = __expf(sf[nt][2] - mn1); rs1 += sf[nt][2];
            sf[nt][3] = __expf(sf[nt][3] - mn1); rs1 += sf[nt][3];
        }
        #pragma unroll
        for (int o = 1; o < 4; o <<= 1) {
            rs0 += __shfl_xor_sync(0xffffffffu, rs0, o);
            rs1 += __shfl_xor_sync(0xffffffffu, rs1, o);
        }
        l0 = l0*al0 + rs0;  m0 = mn0;
        l1 = l1*al1 + rs1;  m1 = mn1;
        #pragma unroll
        for (int nt = 0; nt < 8; nt++) {
            oacc[nt][0] *= al0; oacc[nt][1] *= al0;
            oacc[nt][2] *= al1; oacc[nt][3] *= al1;
        }

        // ---- write P (C-layout -> smem), re-read as A-fragments
        __syncwarp();
        #pragma unroll
        for (int nt = 0; nt < 8; nt++) {
            Pw[ g     *PADP + nt*8 + 2*t    ] = tf32r(sf[nt][0]);
            Pw[ g     *PADP + nt*8 + 2*t + 1] = tf32r(sf[nt][1]);
            Pw[(g + 8)*PADP + nt*8 + 2*t    ] = tf32r(sf[nt][2]);
            Pw[(g + 8)*PADP + nt*8 + 2*t + 1] = tf32r(sf[nt][3]);
        }
        __syncwarp();

        // ---- O += P V
        #pragma unroll
        for (int ks = 0; ks < 8; ks++) {
            uint32_t pa[4];
            pa[0] = fau(Pw[ g     *PADP + ks*8 + t    ]);
            pa[1] = fau(Pw[(g + 8)*PADP + ks*8 + t    ]);
            pa[2] = fau(Pw[ g     *PADP + ks*8 + t + 4]);
            pa[3] = fau(Pw[(g + 8)*PADP + ks*8 + t + 4]);
            #pragma unroll
            for (int dt = 0; dt < 8; dt++) {
                const uint32_t b0 = fau(Vs[(ks*8 + t    )*PADV + dt*8 + g]);
                const uint32_t b1 = fau(Vs[(ks*8 + t + 4)*PADV + dt*8 + g]);
                mma_tf32(oacc[dt], pa, b0, b1);
            }
        }
    }

    // ---- epilogue: normalize, tf32-round, coalesced store via Pw
    const float inv0 = 1.0f / l0, inv1 = 1.0f / l1;
    __syncwarp();
    #pragma unroll
    for (int dt = 0; dt < 8; dt++) {
        Pw[ g     *PADP + dt*8 + 2*t    ] = tf32r(oacc[dt][0] * inv0);
        Pw[ g     *PADP + dt*8 + 2*t + 1] = tf32r(oacc[dt][1] * inv0);
        Pw[(g + 8)*PADP + dt*8 + 2*t    ] = tf32r(oacc[dt][2] * inv1);
        Pw[(g + 8)*PADP + dt*8 + 2*t + 1] = tf32r(oacc[dt][3] * inv1);
    }
    __syncwarp();
    for (int i = lane; i < 16*64; i += 32) {
        const int r = i >> 6, d = i & 63;
        Og[(long)(qw + r)*EMB + d] = Pw[r*PADP + d];
    }
}

// ---------------------------------------------------------------------------
// Kernel 3: output projection  C[8192,1024] = O @ Wo^T + bo, tf32 mma.
//   Tiles 128(M) x 64(N) x 32(K); 8 warps, warp tile 16x64.
//   Pads = 36 -> fragment banks (4g + t + 8s) mod 32: conflict-free.
// ---------------------------------------------------------------------------
#define OPADA 36
#define OPADB 36

__global__ __launch_bounds__(256)
void outproj_kernel(const float* __restrict__ Wo, const float* __restrict__ bo,
                    float* __restrict__ Cout)
{
    __shared__ float As[128*OPADA];
    __shared__ float Bs[64*OPADB];

    const int tid  = threadIdx.x;
    const int lane = tid & 31;
    const int w    = tid >> 5;
    const int g    = lane >> 2;
    const int t    = lane & 3;

    const int mbase = blockIdx.x * 128;   // 64 blocks
    const int ebase = blockIdx.y * 64;    // 16 blocks

    float acc[8][4];
    #pragma unroll
    for (int i = 0; i < 8; i++)
        #pragma unroll
        for (int j = 0; j < 4; j++) acc[i][j] = 0.f;

    for (int kb = 0; kb < EMB; kb += 32) {
        __syncthreads();
        for (int i = tid; i < 128*32; i += 256) {
            const int m = i >> 5, k = i & 31;
            As[m*OPADA + k] = g_O[(long)(mbase + m)*EMB + kb + k];   // already tf32
        }
        for (int i = tid; i < 64*32; i += 256) {
            const int e = i >> 5, k = i & 31;
            Bs[e*OPADB + k] = tf32r(Wo[(long)(ebase + e)*EMB + kb + k]);
        }
        __syncthreads();

        #pragma unroll
        for (int s = 0; s < 4; s++) {
            uint32_t a[4];
            a[0] = fau(As[(w*16 + g    )*OPADA + s*8 + t    ]);
            a[1] = fau(As[(w*16 + g + 8)*OPADA + s*8 + t    ]);
            a[2] = fau(As[(w*16 + g    )*OPADA + s*8 + t + 4]);
            a[3] = fau(As[(w*16 + g + 8)*OPADA + s*8 + t + 4]);
            #pragma unroll
            for (int nt = 0; nt < 8; nt++) {
                const uint32_t b0 = fau(Bs[(nt*8 + g)*OPADB + s*8 + t    ]);
                const uint32_t b1 = fau(Bs[(nt*8 + g)*OPADB + s*8 + t + 4]);
                mma_tf32(acc[nt], a, b0, b1);
            }
        }
    }

    // epilogue: + bias, float2 stores (c0,c1 / c2,c3 are adjacent columns)
    const long row0 = mbase + w*16 + g;
    const long row1 = row0 + 8;
    #pragma unroll
    for (int nt = 0; nt < 8; nt++) {
        const int e = ebase + nt*8 + 2*t;
        const float b0 = bo[e], b1 = bo[e + 1];
        *(float2*)&Cout[row0*EMB + e] = make_float2(acc[nt][0] + b0, acc[nt][1] + b1);
        *(float2*)&Cout[row1*EMB + e] = make_float2(acc[nt][2] + b0, acc[nt][3] + b1);
    }
}

// ---------------------------------------------------------------------------
// Launch.  Inputs (metadata order): values, keys, query, Wv, Wk, Wq, Wo, bo.
// ---------------------------------------------------------------------------
extern "C" void kernel_launch(void* const* d_in, const int* in_sizes, int n_in,
                              void* d_out, int out_size)
{
    const float* Vin = (const float*)d_in[0];
    const float* Kin = (const float*)d_in[1];
    const float* Qin = (const float*)d_in[2];
    const float* Wv  = (const float*)d_in[3];
    const float* Wk  = (const float*)d_in[4];
    const float* Wq  = (const float*)d_in[5];
    const float* Wo  = (const float*)d_in[6];
    const float* bo  = (const float*)d_in[7];
    float* out = (float*)d_out;

    cudaFuncSetAttribute(attn_kernel, cudaFuncAttributeMaxDynamicSharedMemorySize,
                         (int)ATTN_SMEM);

    proj_kernel<<<MTOT/512, 256>>>(Vin, Kin, Qin, Wv, Wk, Wq);
    attn_kernel<<<dim3(16, NB*NH), 256, ATTN_SMEM>>>();
    outproj_kernel<<<dim3((NB*SEQ)/128, EMB/64), 256>>>(Wo, bo, out);
}